// round 12
// baseline (speedup 1.0000x reference)
#include <cuda_runtime.h>
#include <cstdint>

#define EMB_DIM  128
#define NB_WORDS 100000

// out[b][e] = W[e * NB_WORDS + elt[b]] + bias[e]
// Champion configuration (R7): 4 batch rows per 512-thread block,
// warp = 32 e-lanes of one batch row (uniform index, 1 coalesced store),
// W gathers policy-pinned evict_last in L2, output stores evict_first.
__global__ void __launch_bounds__(512)
time_embedding_kernel(const int* __restrict__ elt,
                      const float* __restrict__ W,
                      const float* __restrict__ bias,
                      float* __restrict__ out,
                      int batch) {
    const int e   = threadIdx.x & (EMB_DIM - 1);   // 0..127
    const int sub = threadIdx.x >> 7;              // 0..3
    const int b   = blockIdx.x * 4 + sub;
    if (b >= batch) return;

    // L2 policies: W lines -> evict_last (retain across graph replays),
    // output lines -> evict_first (streaming; don't displace W).
    uint64_t pol_last, pol_first;
    asm volatile("createpolicy.fractional.L2::evict_last.b64 %0, 1.0;"
                 : "=l"(pol_last));
    asm volatile("createpolicy.fractional.L2::evict_first.b64 %0, 1.0;"
                 : "=l"(pol_first));

    const int idx = __ldg(&elt[b]);                // warp-uniform broadcast
    const float* wp = &W[(size_t)e * NB_WORDS + idx];

    float w;
    asm volatile("ld.global.nc.L2::cache_hint.f32 %0, [%1], %2;"
                 : "=f"(w) : "l"(wp), "l"(pol_last));

    const float bv = __ldg(&bias[e]);
    float* op = &out[(size_t)b * EMB_DIM + e];
    const float val = w + bv;
    asm volatile("st.global.L2::cache_hint.f32 [%0], %1, %2;"
                 :: "l"(op), "f"(val), "l"(pol_first) : "memory");
}

extern "C" void kernel_launch(void* const* d_in, const int* in_sizes, int n_in,
                              void* d_out, int out_size) {
    const int* elt  = (const int*)d_in[0];
    const float* W  = (const float*)d_in[1];
    const float* bv = (const float*)d_in[2];
    float* out      = (float*)d_out;
    const int batch = in_sizes[0];                 // 4096

    time_embedding_kernel<<<(batch + 3) / 4, 512>>>(elt, W, bv, out, batch);
}

// round 13
// speedup vs baseline: 1.0036x; 1.0036x over previous
#include <cuda_runtime.h>
#include <cstdint>

#define EMB_DIM  128
#define NB_WORDS 100000

// out[b][e] = W[e * NB_WORDS + elt[b]] + bias[e]
// Warp = one batch row. Each lane owns 4 consecutive e's:
//   e = lane*4 + k  ->  4 independent policy-hinted gathers, one STG.128.
// 256 threads = 8 rows per block, 512 blocks.
__global__ void __launch_bounds__(256)
time_embedding_kernel(const int* __restrict__ elt,
                      const float* __restrict__ W,
                      const float* __restrict__ bias,
                      float* __restrict__ out,
                      int batch) {
    const int lane = threadIdx.x & 31;
    const int wrp  = threadIdx.x >> 5;             // 0..7
    const int b    = blockIdx.x * 8 + wrp;
    if (b >= batch) return;

    const int e0 = lane * 4;                       // 4 consecutive e's per lane

    // L2 policies: W -> evict_last (retained across graph replays),
    // out -> evict_first (streaming; don't displace W).
    uint64_t pol_last, pol_first;
    asm volatile("createpolicy.fractional.L2::evict_last.b64 %0, 1.0;"
                 : "=l"(pol_last));
    asm volatile("createpolicy.fractional.L2::evict_first.b64 %0, 1.0;"
                 : "=l"(pol_first));

    const int idx = __ldg(&elt[b]);                // warp-uniform broadcast

    // bias: one coalesced float4 per lane
    const float4 bv = *(const float4*)(bias + e0);

    // 4 independent scattered gathers (64B fills, L2-pinned)
    const float* wp = W + (size_t)e0 * NB_WORDS + idx;
    float w0, w1, w2, w3;
    asm volatile("ld.global.nc.L2::cache_hint.L2::64B.f32 %0, [%1], %2;"
                 : "=f"(w0) : "l"(wp), "l"(pol_last));
    asm volatile("ld.global.nc.L2::cache_hint.L2::64B.f32 %0, [%1], %2;"
                 : "=f"(w1) : "l"(wp + (size_t)NB_WORDS), "l"(pol_last));
    asm volatile("ld.global.nc.L2::cache_hint.L2::64B.f32 %0, [%1], %2;"
                 : "=f"(w2) : "l"(wp + (size_t)2 * NB_WORDS), "l"(pol_last));
    asm volatile("ld.global.nc.L2::cache_hint.L2::64B.f32 %0, [%1], %2;"
                 : "=f"(w3) : "l"(wp + (size_t)3 * NB_WORDS), "l"(pol_last));

    // One 128-bit store per lane; warp covers the full 512B output row.
    float4 v;
    v.x = w0 + bv.x;
    v.y = w1 + bv.y;
    v.z = w2 + bv.z;
    v.w = w3 + bv.w;
    float* op = out + (size_t)b * EMB_DIM + e0;
    asm volatile("st.global.L2::cache_hint.v4.f32 [%0], {%1,%2,%3,%4}, %5;"
                 :: "l"(op), "f"(v.x), "f"(v.y), "f"(v.z), "f"(v.w),
                    "l"(pol_first) : "memory");
}

extern "C" void kernel_launch(void* const* d_in, const int* in_sizes, int n_in,
                              void* d_out, int out_size) {
    const int* elt  = (const int*)d_in[0];
    const float* W  = (const float*)d_in[1];
    const float* bv = (const float*)d_in[2];
    float* out      = (float*)d_out;
    const int batch = in_sizes[0];                 // 4096

    time_embedding_kernel<<<(batch + 7) / 8, 256>>>(elt, W, bv, out, batch);
}

// round 14
// speedup vs baseline: 1.0728x; 1.0690x over previous
#include <cuda_runtime.h>
#include <cstdint>

#define EMB_DIM  128
#define NB_WORDS 100000

// out[b][e] = W[e * NB_WORDS + elt[b]] + bias[e]
// Warp = 2 batch rows; lane owns 4 consecutive e's (e = lane*4 + k).
// Per thread: 8 front-batched gathers (MLP=8), 2 x STG.128.
// 256 threads = 8 warps = 16 rows per block; 256 blocks.
__global__ void __launch_bounds__(256)
time_embedding_kernel(const int* __restrict__ elt,
                      const float* __restrict__ W,
                      const float* __restrict__ bias,
                      float* __restrict__ out,
                      int batch) {
    const int lane = threadIdx.x & 31;
    const int wrp  = threadIdx.x >> 5;              // 0..7
    const int b0   = blockIdx.x * 16 + wrp * 2;     // first of 2 rows
    const int e0   = lane * 4;

    // L2 policies: W -> evict_last (retained across graph replays),
    // out -> evict_first (streaming; don't displace W).
    uint64_t pol_last, pol_first;
    asm volatile("createpolicy.fractional.L2::evict_last.b64 %0, 1.0;"
                 : "=l"(pol_last));
    asm volatile("createpolicy.fractional.L2::evict_first.b64 %0, 1.0;"
                 : "=l"(pol_first));

    const bool v0 = (b0 < batch);
    const bool v1 = (b0 + 1 < batch);
    const int idx0 = v0 ? __ldg(&elt[b0])     : 0;  // warp-uniform broadcasts
    const int idx1 = v1 ? __ldg(&elt[b0 + 1]) : 0;

    const float4 bv = *(const float4*)(bias + e0);  // coalesced

    // 8 independent scattered gathers, front-batched (MLP=8), 64B fills.
    const float* wbase = W + (size_t)e0 * NB_WORDS;
    float a0, a1, a2, a3, c0, c1, c2, c3;
    #define LDW(dst, off) \
        asm volatile("ld.global.nc.L2::cache_hint.L2::64B.f32 %0, [%1], %2;" \
                     : "=f"(dst) : "l"(wbase + (off)), "l"(pol_last))
    LDW(a0, (size_t)0 * NB_WORDS + idx0);
    LDW(a1, (size_t)1 * NB_WORDS + idx0);
    LDW(a2, (size_t)2 * NB_WORDS + idx0);
    LDW(a3, (size_t)3 * NB_WORDS + idx0);
    LDW(c0, (size_t)0 * NB_WORDS + idx1);
    LDW(c1, (size_t)1 * NB_WORDS + idx1);
    LDW(c2, (size_t)2 * NB_WORDS + idx1);
    LDW(c3, (size_t)3 * NB_WORDS + idx1);
    #undef LDW

    if (v0) {
        float* op = out + (size_t)b0 * EMB_DIM + e0;
        const float x0 = a0 + bv.x, x1 = a1 + bv.y, x2 = a2 + bv.z, x3 = a3 + bv.w;
        asm volatile("st.global.L2::cache_hint.v4.f32 [%0], {%1,%2,%3,%4}, %5;"
                     :: "l"(op), "f"(x0), "f"(x1), "f"(x2), "f"(x3),
                        "l"(pol_first) : "memory");
    }
    if (v1) {
        float* op = out + (size_t)(b0 + 1) * EMB_DIM + e0;
        const float y0 = c0 + bv.x, y1 = c1 + bv.y, y2 = c2 + bv.z, y3 = c3 + bv.w;
        asm volatile("st.global.L2::cache_hint.v4.f32 [%0], {%1,%2,%3,%4}, %5;"
                     :: "l"(op), "f"(y0), "f"(y1), "f"(y2), "f"(y3),
                        "l"(pol_first) : "memory");
    }
}

extern "C" void kernel_launch(void* const* d_in, const int* in_sizes, int n_in,
                              void* d_out, int out_size) {
    const int* elt  = (const int*)d_in[0];
    const float* W  = (const float*)d_in[1];
    const float* bv = (const float*)d_in[2];
    float* out      = (float*)d_out;
    const int batch = in_sizes[0];                  // 4096

    time_embedding_kernel<<<(batch + 15) / 16, 256>>>(elt, W, bv, out, batch);
}